// round 15
// baseline (speedup 1.0000x reference)
#include <cuda_runtime.h>
#include <cuda_fp16.h>
#include <cstdint>

// Problem dims (fixed by the dataset)
#define SEQ  2048
#define OUTF 8192
#define INF  8192

// Scratch (device globals are the sanctioned no-cudaMalloc scratch)
__device__ __half g_Wh[(size_t)OUTF * INF];   // 128 MiB dequantized weights, [O][K]
__device__ __half g_Xh[(size_t)SEQ  * INF];   //  32 MiB fp16 activations,   [S][K]

// ---------------------------------------------------------------------------
// PTX helpers — baseline (non-'a') ISA only: cp.async / ldmatrix / mma.sync
// ---------------------------------------------------------------------------
__device__ __forceinline__ uint32_t smem_u32(const void* p) {
    uint32_t r;
    asm("{ .reg .u64 t; cvta.to.shared.u64 t, %1; cvt.u32.u64 %0, t; }"
        : "=r"(r) : "l"(p));
    return r;
}

__device__ __forceinline__ void cp16(uint32_t saddr, const void* g) {
    asm volatile("cp.async.cg.shared.global [%0], [%1], 16;"
                 :: "r"(saddr), "l"(g) : "memory");
}
__device__ __forceinline__ void cp_commit() {
    asm volatile("cp.async.commit_group;" ::: "memory");
}
template <int N>
__device__ __forceinline__ void cp_wait() {
    asm volatile("cp.async.wait_group %0;" :: "n"(N) : "memory");
}

#define LDSM4(r, addr) \
    asm volatile("ldmatrix.sync.aligned.m8n8.x4.shared.b16 {%0,%1,%2,%3}, [%4];" \
                 : "=r"((r)[0]), "=r"((r)[1]), "=r"((r)[2]), "=r"((r)[3])        \
                 : "r"(addr))

#define MMA16816(d, a, b0, b1)                                                  \
    asm volatile("mma.sync.aligned.m16n8k16.row.col.f32.f16.f16.f32 "           \
                 "{%0,%1,%2,%3}, {%4,%5,%6,%7}, {%8,%9}, {%0,%1,%2,%3};"        \
                 : "+f"((d)[0]), "+f"((d)[1]), "+f"((d)[2]), "+f"((d)[3])       \
                 : "r"((a)[0]), "r"((a)[1]), "r"((a)[2]), "r"((a)[3]),          \
                   "r"(b0), "r"(b1))

// ---------------------------------------------------------------------------
// Fused prep kernel (heterogeneous grid):
//   blocks [0, 1024)        : dequant qweight -> g_Wh via per-row pair LUT
//   blocks [1024, 1024+4096): x fp32 -> fp16 into g_Xh (4 float4 per thread)
// ---------------------------------------------------------------------------
#define DQ_BLOCKS  (OUTF / 8)                 // 1024
#define CVT_BLOCKS ((SEQ * INF / 4) / 1024)   // 4096
#define PREP_GRID  (DQ_BLOCKS + CVT_BLOCKS)   // 5120

__device__ __forceinline__ void dq_word(uint32_t wd, const uint32_t* pl,
                                        uint32_t& a, uint32_t& b) {
    uint32_t t = (wd >> 4) & 0x0F0F0F0Fu;  // byte c = idx_c (top nibble of code c)
    uint32_t u = t | (t >> 4);             // byte0 = idx0|idx1<<4, byte2 = idx2|idx3<<4
    a = pl[u & 0xFFu];
    b = pl[(u >> 16) & 0xFFu];
}

__global__ void __launch_bounds__(256) prep_kernel(const float* __restrict__ x,
                                                   const int* __restrict__ qw,
                                                   const float* __restrict__ lutp) {
    __shared__ uint32_t plut[8][256];
    const int bid = blockIdx.x;
    const int tid = threadIdx.x;

    if (bid < DQ_BLOCKS) {
        // ---- dequant branch ----
        const int w = tid >> 5, lid = tid & 31;
        const int row = bid * 8 + w;

        float lv = lutp[row * 16 + (lid & 15)];
        #pragma unroll
        for (int e = lid; e < 256; e += 32) {
            float lo = __shfl_sync(0xffffffffu, lv, e & 15);
            float hi = __shfl_sync(0xffffffffu, lv, (e >> 4) & 15);
            __half2 h = __floats2half2_rn(lo, hi);
            plut[w][e] = *reinterpret_cast<uint32_t*>(&h);
        }
        __syncwarp();

        const int4* qrow = reinterpret_cast<const int4*>(qw) + (size_t)row * (INF / 16);
        int4* orow = reinterpret_cast<int4*>(g_Wh + (size_t)row * INF);
        const uint32_t* pl = plut[w];

        #pragma unroll 4
        for (int i = lid; i < INF / 16; i += 32) {   // 512 int4 words per row
            int4 q = qrow[i];
            uint32_t o0, o1, o2, o3, o4, o5, o6, o7;
            dq_word((uint32_t)q.x, pl, o0, o1);
            dq_word((uint32_t)q.y, pl, o2, o3);
            dq_word((uint32_t)q.z, pl, o4, o5);
            dq_word((uint32_t)q.w, pl, o6, o7);
            orow[2 * i]     = make_int4((int)o0, (int)o1, (int)o2, (int)o3);
            orow[2 * i + 1] = make_int4((int)o4, (int)o5, (int)o6, (int)o7);
        }
    } else {
        // ---- fp32 -> fp16 convert branch ----
        const int cb = bid - DQ_BLOCKS;              // 0 .. 4095
        const int base = cb * 1024;                  // float4 units
        #pragma unroll
        for (int j = 0; j < 4; j++) {
            int i = base + j * 256 + tid;
            float4 v = reinterpret_cast<const float4*>(x)[i];
            __half2 a = __floats2half2_rn(v.x, v.y);
            __half2 b = __floats2half2_rn(v.z, v.w);
            uint2 st = make_uint2(*reinterpret_cast<uint32_t*>(&a),
                                  *reinterpret_cast<uint32_t*>(&b));
            reinterpret_cast<uint2*>(g_Xh)[i] = st;
        }
    }
}

// ---------------------------------------------------------------------------
// GEMM: out[m][n] = sum_k Xh[m][k]*Wh[n][k]
//   R13 config (best: 665us GEMM, tensor=69.5%): persistent 296 CTAs,
//   CTA 128x128x32, 4 warps (64x64 warp tile), 2 CTAs/SM, 4-stage cp.async,
//   RSTR=40 pad (conflict-free ldmatrix), N-fast tile raster.
//   R15 (only change vs R13): kt body manually unrolled over the 2 K-steps
//   and the next-stage cp.async issue moved to right after the ks0 fragment
//   loads, so its LSU issue + flight hides under the 64 ks0 MMAs. One frag
//   buffer pair live at a time -> regs stay ~224 (no spills).
// ---------------------------------------------------------------------------
#define BM 128
#define BN 128
#define BK 32
#define NSTG 4
#define RSTR 40                         // halves per padded row
#define A_ELE (BM * RSTR)               // 5120 halves
#define B_ELE (BN * RSTR)               // 5120 halves
#define STG_ELE (A_ELE + B_ELE)         // 10240 halves (20 KB)
#define SMEM_BYTES (NSTG * STG_ELE * 2) // 81920 B per CTA (x2 = 160 KB/SM)
#define NK (INF / BK)                   // 256 k-iters
#define NTILE_N (OUTF / BN)             // 64
#define NTILES  (NTILE_N * (SEQ / BM))  // 1024
#define GRID_CTAS 296                   // 2 CTAs/SM x 148 SMs

__global__ void __launch_bounds__(128, 2) gemm_kernel(float* __restrict__ out) {
    extern __shared__ __half sm[];
    const uint32_t sbase = smem_u32(sm);
    const int tid = threadIdx.x;
    const int wid = tid >> 5, lane = tid & 31;
    const int wm = (wid & 1) * 64;       // warp tile M offset in CTA
    const int wn = (wid >> 1) * 64;      // warp tile N offset in CTA

    // ldmatrix per-lane row/col-chunk mapping (matches m16n8k16 frag layouts)
    const int a_row = ((lane >> 3) & 1) * 8 + (lane & 7);  // + kc = lane>>4
    const int a_kc  = lane >> 4;
    const int b_row = ((lane >> 4) << 3) + (lane & 7);     // + kc = (lane>>3)&1
    const int b_kc  = (lane >> 3) & 1;

    uint32_t sA[4], sB[4];
    #pragma unroll
    for (int i = 0; i < 4; i++) {
        int idx = tid + i * 128;
        int r = idx >> 2, c = idx & 3;
        sA[i] = (uint32_t)(r * RSTR + c * 8) * 2;
        sB[i] = (uint32_t)(A_ELE + r * RSTR + c * 8) * 2;
    }
    const int er = lane >> 2, ec = (lane & 3) * 2;         // epilogue lane map

    #pragma unroll 1
    for (int t = blockIdx.x; t < NTILES; t += GRID_CTAS) {
        const int n0 = (t % NTILE_N) * BN;   // N fast
        const int m0 = (t / NTILE_N) * BM;

        // make smem safe for reuse (prior tile's reads / cp groups done)
        cp_wait<0>();
        __syncthreads();

        const __half* gA[4]; const __half* gB[4];
        #pragma unroll
        for (int i = 0; i < 4; i++) {
            int idx = tid + i * 128;
            int r = idx >> 2, c = idx & 3;
            gA[i] = g_Xh + (size_t)(m0 + r) * INF + c * 8;
            gB[i] = g_Wh + (size_t)(n0 + r) * INF + c * 8;
        }

        float acc[4][8][4];
        #pragma unroll
        for (int mi = 0; mi < 4; mi++)
            #pragma unroll
            for (int nj = 0; nj < 8; nj++)
                acc[mi][nj][0] = acc[mi][nj][1] = acc[mi][nj][2] = acc[mi][nj][3] = 0.f;

        auto issue = [&](int kt, int s) {
            const uint32_t so = sbase + (uint32_t)(s * STG_ELE) * 2;
            const int ko = kt * BK;
            #pragma unroll
            for (int i = 0; i < 4; i++) {
                cp16(so + sA[i], gA[i] + ko);
                cp16(so + sB[i], gB[i] + ko);
            }
        };

        #pragma unroll
        for (int s = 0; s < NSTG - 1; s++) { issue(s, s); cp_commit(); }

        #pragma unroll 1
        for (int kt = 0; kt < NK; kt++) {
            cp_wait<NSTG - 2>();
            __syncthreads();

            const uint32_t sa = sbase + (uint32_t)((kt % NSTG) * STG_ELE) * 2;
            const uint32_t sb = sa + (uint32_t)A_ELE * 2;

            // ---- ks0 fragment loads ----
            uint32_t a[4][4], b[4][4];
            #pragma unroll
            for (int mi = 0; mi < 4; mi++)
                LDSM4(a[mi], sa + (uint32_t)((wm + mi * 16 + a_row) * RSTR
                                             + a_kc * 8) * 2);
            #pragma unroll
            for (int p = 0; p < 4; p++)
                LDSM4(b[p], sb + (uint32_t)((wn + p * 16 + b_row) * RSTR
                                            + b_kc * 8) * 2);

            // ---- issue next stage NOW: rides under the 64 ks0 MMAs ----
            const int nk = kt + NSTG - 1;
            if (nk < NK) issue(nk, nk % NSTG);
            cp_commit();

            // ---- ks0 MMAs ----
            #pragma unroll
            for (int mi = 0; mi < 4; mi++)
                #pragma unroll
                for (int nj = 0; nj < 8; nj++)
                    MMA16816(acc[mi][nj], a[mi],
                             b[nj >> 1][(nj & 1) * 2], b[nj >> 1][(nj & 1) * 2 + 1]);

            // ---- ks1 fragment loads (reuse buffers) + MMAs ----
            #pragma unroll
            for (int mi = 0; mi < 4; mi++)
                LDSM4(a[mi], sa + (uint32_t)((wm + mi * 16 + a_row) * RSTR
                                             + 16 + a_kc * 8) * 2);
            #pragma unroll
            for (int p = 0; p < 4; p++)
                LDSM4(b[p], sb + (uint32_t)((wn + p * 16 + b_row) * RSTR
                                            + 16 + b_kc * 8) * 2);
            #pragma unroll
            for (int mi = 0; mi < 4; mi++)
                #pragma unroll
                for (int nj = 0; nj < 8; nj++)
                    MMA16816(acc[mi][nj], a[mi],
                             b[nj >> 1][(nj & 1) * 2], b[nj >> 1][(nj & 1) * 2 + 1]);
        }

        // Epilogue: c0,c1 -> (row lane/4, col (lane%4)*2); c2,c3 -> row+8
        #pragma unroll
        for (int mi = 0; mi < 4; mi++) {
            #pragma unroll
            for (int nj = 0; nj < 8; nj++) {
                float* p = out + (size_t)(m0 + wm + mi * 16 + er) * OUTF
                               + (n0 + wn + nj * 8 + ec);
                *reinterpret_cast<float2*>(p) =
                    make_float2(acc[mi][nj][0], acc[mi][nj][1]);
                *reinterpret_cast<float2*>(p + 8 * OUTF) =
                    make_float2(acc[mi][nj][2], acc[mi][nj][3]);
            }
        }
    }
}

// ---------------------------------------------------------------------------
extern "C" void kernel_launch(void* const* d_in, const int* in_sizes, int n_in,
                              void* d_out, int out_size) {
    const float* x   = (const float*)d_in[0];   // (1, 2048, 8192) fp32
    const int*   qw  = (const int*)  d_in[1];   // (8192, 2048)    int32
    const float* lut = (const float*)d_in[2];   // (8192, 16)      fp32
    float* out = (float*)d_out;                 // (1, 2048, 8192) fp32

    cudaFuncSetAttribute(gemm_kernel,
                         cudaFuncAttributeMaxDynamicSharedMemorySize, SMEM_BYTES);

    prep_kernel<<<PREP_GRID, 256>>>(x, qw, lut);
    gemm_kernel<<<GRID_CTAS, 128, SMEM_BYTES>>>(out);
}

// round 16
// speedup vs baseline: 1.1621x; 1.1621x over previous
#include <cuda_runtime.h>
#include <cuda_fp16.h>
#include <cstdint>

// Problem dims (fixed by the dataset)
#define SEQ  2048
#define OUTF 8192
#define INF  8192

// Scratch (device globals are the sanctioned no-cudaMalloc scratch)
__device__ __half g_Wh[(size_t)OUTF * INF];   // 128 MiB dequantized weights, [O][K]
__device__ __half g_Xh[(size_t)SEQ  * INF];   //  32 MiB fp16 activations,   [S][K]

// ---------------------------------------------------------------------------
// PTX helpers — baseline (non-'a') ISA only: cp.async / ldmatrix / mma.sync
// ---------------------------------------------------------------------------
__device__ __forceinline__ uint32_t smem_u32(const void* p) {
    uint32_t r;
    asm("{ .reg .u64 t; cvta.to.shared.u64 t, %1; cvt.u32.u64 %0, t; }"
        : "=r"(r) : "l"(p));
    return r;
}

__device__ __forceinline__ void cp16(uint32_t saddr, const void* g) {
    asm volatile("cp.async.cg.shared.global [%0], [%1], 16;"
                 :: "r"(saddr), "l"(g) : "memory");
}
__device__ __forceinline__ void cp_commit() {
    asm volatile("cp.async.commit_group;" ::: "memory");
}
template <int N>
__device__ __forceinline__ void cp_wait() {
    asm volatile("cp.async.wait_group %0;" :: "n"(N) : "memory");
}

#define LDSM4(r, addr) \
    asm volatile("ldmatrix.sync.aligned.m8n8.x4.shared.b16 {%0,%1,%2,%3}, [%4];" \
                 : "=r"((r)[0]), "=r"((r)[1]), "=r"((r)[2]), "=r"((r)[3])        \
                 : "r"(addr))

#define MMA16816(d, a, b0, b1)                                                  \
    asm volatile("mma.sync.aligned.m16n8k16.row.col.f32.f16.f16.f32 "           \
                 "{%0,%1,%2,%3}, {%4,%5,%6,%7}, {%8,%9}, {%0,%1,%2,%3};"        \
                 : "+f"((d)[0]), "+f"((d)[1]), "+f"((d)[2]), "+f"((d)[3])       \
                 : "r"((a)[0]), "r"((a)[1]), "r"((a)[2]), "r"((a)[3]),          \
                   "r"(b0), "r"(b1))

// ---------------------------------------------------------------------------
// Fused prep kernel (heterogeneous grid):
//   blocks [0, 1024)        : dequant qweight -> g_Wh via per-row pair LUT
//   blocks [1024, 1024+4096): x fp32 -> fp16 into g_Xh (4 float4 per thread)
//   Measured at the HBM roofline (288 MB moved in ~36us) — do not touch.
// ---------------------------------------------------------------------------
#define DQ_BLOCKS  (OUTF / 8)                 // 1024
#define CVT_BLOCKS ((SEQ * INF / 4) / 1024)   // 4096
#define PREP_GRID  (DQ_BLOCKS + CVT_BLOCKS)   // 5120

__device__ __forceinline__ void dq_word(uint32_t wd, const uint32_t* pl,
                                        uint32_t& a, uint32_t& b) {
    uint32_t t = (wd >> 4) & 0x0F0F0F0Fu;  // byte c = idx_c (top nibble of code c)
    uint32_t u = t | (t >> 4);             // byte0 = idx0|idx1<<4, byte2 = idx2|idx3<<4
    a = pl[u & 0xFFu];
    b = pl[(u >> 16) & 0xFFu];
}

__global__ void __launch_bounds__(256) prep_kernel(const float* __restrict__ x,
                                                   const int* __restrict__ qw,
                                                   const float* __restrict__ lutp) {
    __shared__ uint32_t plut[8][256];
    const int bid = blockIdx.x;
    const int tid = threadIdx.x;

    if (bid < DQ_BLOCKS) {
        // ---- dequant branch ----
        const int w = tid >> 5, lid = tid & 31;
        const int row = bid * 8 + w;

        float lv = lutp[row * 16 + (lid & 15)];
        #pragma unroll
        for (int e = lid; e < 256; e += 32) {
            float lo = __shfl_sync(0xffffffffu, lv, e & 15);
            float hi = __shfl_sync(0xffffffffu, lv, (e >> 4) & 15);
            __half2 h = __floats2half2_rn(lo, hi);
            plut[w][e] = *reinterpret_cast<uint32_t*>(&h);
        }
        __syncwarp();

        const int4* qrow = reinterpret_cast<const int4*>(qw) + (size_t)row * (INF / 16);
        int4* orow = reinterpret_cast<int4*>(g_Wh + (size_t)row * INF);
        const uint32_t* pl = plut[w];

        #pragma unroll 4
        for (int i = lid; i < INF / 16; i += 32) {   // 512 int4 words per row
            int4 q = qrow[i];
            uint32_t o0, o1, o2, o3, o4, o5, o6, o7;
            dq_word((uint32_t)q.x, pl, o0, o1);
            dq_word((uint32_t)q.y, pl, o2, o3);
            dq_word((uint32_t)q.z, pl, o4, o5);
            dq_word((uint32_t)q.w, pl, o6, o7);
            orow[2 * i]     = make_int4((int)o0, (int)o1, (int)o2, (int)o3);
            orow[2 * i + 1] = make_int4((int)o4, (int)o5, (int)o6, (int)o7);
        }
    } else {
        // ---- fp32 -> fp16 convert branch ----
        const int cb = bid - DQ_BLOCKS;              // 0 .. 4095
        const int base = cb * 1024;                  // float4 units
        #pragma unroll
        for (int j = 0; j < 4; j++) {
            int i = base + j * 256 + tid;
            float4 v = reinterpret_cast<const float4*>(x)[i];
            __half2 a = __floats2half2_rn(v.x, v.y);
            __half2 b = __floats2half2_rn(v.z, v.w);
            uint2 st = make_uint2(*reinterpret_cast<uint32_t*>(&a),
                                  *reinterpret_cast<uint32_t*>(&b));
            reinterpret_cast<uint2*>(g_Xh)[i] = st;
        }
    }
}

// ---------------------------------------------------------------------------
// GEMM: out[m][n] = sum_k Xh[m][k]*Wh[n][k]
//   FROZEN R13 mainloop (best measured: 665us, tensor=69.5%; every manual
//   reordering attempt — BK=64, frag hoist, early cp.async issue — regressed).
//   Persistent 296 CTAs, CTA 128x128x32, 4 warps (64x64 warp tile), 2 CTAs/SM,
//   RSTR=40 pad (conflict-free ldmatrix), N-fast tile raster.
//   R16 single change: NSTG 4 -> 5 (one extra stage of slack vs L2 jitter;
//   200 KB/SM smem, occupancy and regs unchanged).
// ---------------------------------------------------------------------------
#define BM 128
#define BN 128
#define BK 32
#define NSTG 5
#define RSTR 40                         // halves per padded row
#define A_ELE (BM * RSTR)               // 5120 halves
#define B_ELE (BN * RSTR)               // 5120 halves
#define STG_ELE (A_ELE + B_ELE)         // 10240 halves (20 KB)
#define SMEM_BYTES (NSTG * STG_ELE * 2) // 102400 B per CTA (x2 = 200 KB/SM)
#define NK (INF / BK)                   // 256 k-iters
#define NTILE_N (OUTF / BN)             // 64
#define NTILES  (NTILE_N * (SEQ / BM))  // 1024
#define GRID_CTAS 296                   // 2 CTAs/SM x 148 SMs

__global__ void __launch_bounds__(128, 2) gemm_kernel(float* __restrict__ out) {
    extern __shared__ __half sm[];
    const uint32_t sbase = smem_u32(sm);
    const int tid = threadIdx.x;
    const int wid = tid >> 5, lane = tid & 31;
    const int wm = (wid & 1) * 64;       // warp tile M offset in CTA
    const int wn = (wid >> 1) * 64;      // warp tile N offset in CTA

    // ldmatrix per-lane row/col-chunk mapping (matches m16n8k16 frag layouts)
    const int a_row = ((lane >> 3) & 1) * 8 + (lane & 7);  // + kc = lane>>4
    const int a_kc  = lane >> 4;
    const int b_row = ((lane >> 4) << 3) + (lane & 7);     // + kc = (lane>>3)&1
    const int b_kc  = (lane >> 3) & 1;

    uint32_t sA[4], sB[4];
    #pragma unroll
    for (int i = 0; i < 4; i++) {
        int idx = tid + i * 128;
        int r = idx >> 2, c = idx & 3;
        sA[i] = (uint32_t)(r * RSTR + c * 8) * 2;
        sB[i] = (uint32_t)(A_ELE + r * RSTR + c * 8) * 2;
    }
    const int er = lane >> 2, ec = (lane & 3) * 2;         // epilogue lane map

    #pragma unroll 1
    for (int t = blockIdx.x; t < NTILES; t += GRID_CTAS) {
        const int n0 = (t % NTILE_N) * BN;   // N fast
        const int m0 = (t / NTILE_N) * BM;

        // make smem safe for reuse (prior tile's reads / cp groups done)
        cp_wait<0>();
        __syncthreads();

        const __half* gA[4]; const __half* gB[4];
        #pragma unroll
        for (int i = 0; i < 4; i++) {
            int idx = tid + i * 128;
            int r = idx >> 2, c = idx & 3;
            gA[i] = g_Xh + (size_t)(m0 + r) * INF + c * 8;
            gB[i] = g_Wh + (size_t)(n0 + r) * INF + c * 8;
        }

        float acc[4][8][4];
        #pragma unroll
        for (int mi = 0; mi < 4; mi++)
            #pragma unroll
            for (int nj = 0; nj < 8; nj++)
                acc[mi][nj][0] = acc[mi][nj][1] = acc[mi][nj][2] = acc[mi][nj][3] = 0.f;

        auto issue = [&](int kt, int s) {
            const uint32_t so = sbase + (uint32_t)(s * STG_ELE) * 2;
            const int ko = kt * BK;
            #pragma unroll
            for (int i = 0; i < 4; i++) {
                cp16(so + sA[i], gA[i] + ko);
                cp16(so + sB[i], gB[i] + ko);
            }
        };

        #pragma unroll
        for (int s = 0; s < NSTG - 1; s++) { issue(s, s); cp_commit(); }

        #pragma unroll 1
        for (int kt = 0; kt < NK; kt++) {
            cp_wait<NSTG - 2>();
            __syncthreads();

            const uint32_t sa = sbase + (uint32_t)((kt % NSTG) * STG_ELE) * 2;
            const uint32_t sb = sa + (uint32_t)A_ELE * 2;

            #pragma unroll
            for (int ks = 0; ks < 2; ks++) {
                uint32_t a[4][4], b[4][4];
                #pragma unroll
                for (int mi = 0; mi < 4; mi++) {
                    uint32_t ad = sa + (uint32_t)((wm + mi * 16 + a_row) * RSTR
                                                  + ks * 16 + a_kc * 8) * 2;
                    LDSM4(a[mi], ad);
                }
                #pragma unroll
                for (int p = 0; p < 4; p++) {
                    uint32_t bd = sb + (uint32_t)((wn + p * 16 + b_row) * RSTR
                                                  + ks * 16 + b_kc * 8) * 2;
                    LDSM4(b[p], bd);
                }
                #pragma unroll
                for (int mi = 0; mi < 4; mi++)
                    #pragma unroll
                    for (int nj = 0; nj < 8; nj++)
                        MMA16816(acc[mi][nj], a[mi],
                                 b[nj >> 1][(nj & 1) * 2], b[nj >> 1][(nj & 1) * 2 + 1]);
            }

            const int nk = kt + NSTG - 1;
            if (nk < NK) issue(nk, nk % NSTG);
            cp_commit();
        }

        // Epilogue: c0,c1 -> (row lane/4, col (lane%4)*2); c2,c3 -> row+8
        #pragma unroll
        for (int mi = 0; mi < 4; mi++) {
            #pragma unroll
            for (int nj = 0; nj < 8; nj++) {
                float* p = out + (size_t)(m0 + wm + mi * 16 + er) * OUTF
                               + (n0 + wn + nj * 8 + ec);
                *reinterpret_cast<float2*>(p) =
                    make_float2(acc[mi][nj][0], acc[mi][nj][1]);
                *reinterpret_cast<float2*>(p + 8 * OUTF) =
                    make_float2(acc[mi][nj][2], acc[mi][nj][3]);
            }
        }
    }
}

// ---------------------------------------------------------------------------
extern "C" void kernel_launch(void* const* d_in, const int* in_sizes, int n_in,
                              void* d_out, int out_size) {
    const float* x   = (const float*)d_in[0];   // (1, 2048, 8192) fp32
    const int*   qw  = (const int*)  d_in[1];   // (8192, 2048)    int32
    const float* lut = (const float*)d_in[2];   // (8192, 16)      fp32
    float* out = (float*)d_out;                 // (1, 2048, 8192) fp32

    cudaFuncSetAttribute(gemm_kernel,
                         cudaFuncAttributeMaxDynamicSharedMemorySize, SMEM_BYTES);

    prep_kernel<<<PREP_GRID, 256>>>(x, qw, lut);
    gemm_kernel<<<GRID_CTAS, 128, SMEM_BYTES>>>(out);
}

// round 17
// speedup vs baseline: 1.2025x; 1.0348x over previous
#include <cuda_runtime.h>
#include <cuda_fp16.h>
#include <cstdint>

// Problem dims (fixed by the dataset)
#define SEQ  2048
#define OUTF 8192
#define INF  8192

// Scratch (device globals are the sanctioned no-cudaMalloc scratch)
__device__ __half g_Wh[(size_t)OUTF * INF];   // 128 MiB dequantized weights, [O][K]
__device__ __half g_Xh[(size_t)SEQ  * INF];   //  32 MiB fp16 activations,   [S][K]

// ---------------------------------------------------------------------------
// PTX helpers — baseline (non-'a') ISA only: cp.async / ldmatrix / mma.sync
// ---------------------------------------------------------------------------
__device__ __forceinline__ uint32_t smem_u32(const void* p) {
    uint32_t r;
    asm("{ .reg .u64 t; cvta.to.shared.u64 t, %1; cvt.u32.u64 %0, t; }"
        : "=r"(r) : "l"(p));
    return r;
}

__device__ __forceinline__ void cp16(uint32_t saddr, const void* g) {
    asm volatile("cp.async.cg.shared.global [%0], [%1], 16;"
                 :: "r"(saddr), "l"(g) : "memory");
}
__device__ __forceinline__ void cp_commit() {
    asm volatile("cp.async.commit_group;" ::: "memory");
}
template <int N>
__device__ __forceinline__ void cp_wait() {
    asm volatile("cp.async.wait_group %0;" :: "n"(N) : "memory");
}

#define LDSM4(r, addr) \
    asm volatile("ldmatrix.sync.aligned.m8n8.x4.shared.b16 {%0,%1,%2,%3}, [%4];" \
                 : "=r"((r)[0]), "=r"((r)[1]), "=r"((r)[2]), "=r"((r)[3])        \
                 : "r"(addr))

#define MMA16816(d, a, b0, b1)                                                  \
    asm volatile("mma.sync.aligned.m16n8k16.row.col.f32.f16.f16.f32 "           \
                 "{%0,%1,%2,%3}, {%4,%5,%6,%7}, {%8,%9}, {%0,%1,%2,%3};"        \
                 : "+f"((d)[0]), "+f"((d)[1]), "+f"((d)[2]), "+f"((d)[3])       \
                 : "r"((a)[0]), "r"((a)[1]), "r"((a)[2]), "r"((a)[3]),          \
                   "r"(b0), "r"(b1))

// ---------------------------------------------------------------------------
// Fused prep kernel (heterogeneous grid):
//   blocks [0, 1024)        : dequant qweight -> g_Wh via per-row pair LUT
//   blocks [1024, 1024+4096): x fp32 -> fp16 into g_Xh (4 float4 per thread)
//   Measured at the HBM roofline (288 MB moved in ~36us) — frozen.
// ---------------------------------------------------------------------------
#define DQ_BLOCKS  (OUTF / 8)                 // 1024
#define CVT_BLOCKS ((SEQ * INF / 4) / 1024)   // 4096
#define PREP_GRID  (DQ_BLOCKS + CVT_BLOCKS)   // 5120

__device__ __forceinline__ void dq_word(uint32_t wd, const uint32_t* pl,
                                        uint32_t& a, uint32_t& b) {
    uint32_t t = (wd >> 4) & 0x0F0F0F0Fu;  // byte c = idx_c (top nibble of code c)
    uint32_t u = t | (t >> 4);             // byte0 = idx0|idx1<<4, byte2 = idx2|idx3<<4
    a = pl[u & 0xFFu];
    b = pl[(u >> 16) & 0xFFu];
}

__global__ void __launch_bounds__(256) prep_kernel(const float* __restrict__ x,
                                                   const int* __restrict__ qw,
                                                   const float* __restrict__ lutp) {
    __shared__ uint32_t plut[8][256];
    const int bid = blockIdx.x;
    const int tid = threadIdx.x;

    if (bid < DQ_BLOCKS) {
        // ---- dequant branch ----
        const int w = tid >> 5, lid = tid & 31;
        const int row = bid * 8 + w;

        float lv = lutp[row * 16 + (lid & 15)];
        #pragma unroll
        for (int e = lid; e < 256; e += 32) {
            float lo = __shfl_sync(0xffffffffu, lv, e & 15);
            float hi = __shfl_sync(0xffffffffu, lv, (e >> 4) & 15);
            __half2 h = __floats2half2_rn(lo, hi);
            plut[w][e] = *reinterpret_cast<uint32_t*>(&h);
        }
        __syncwarp();

        const int4* qrow = reinterpret_cast<const int4*>(qw) + (size_t)row * (INF / 16);
        int4* orow = reinterpret_cast<int4*>(g_Wh + (size_t)row * INF);
        const uint32_t* pl = plut[w];

        #pragma unroll 4
        for (int i = lid; i < INF / 16; i += 32) {   // 512 int4 words per row
            int4 q = qrow[i];
            uint32_t o0, o1, o2, o3, o4, o5, o6, o7;
            dq_word((uint32_t)q.x, pl, o0, o1);
            dq_word((uint32_t)q.y, pl, o2, o3);
            dq_word((uint32_t)q.z, pl, o4, o5);
            dq_word((uint32_t)q.w, pl, o6, o7);
            orow[2 * i]     = make_int4((int)o0, (int)o1, (int)o2, (int)o3);
            orow[2 * i + 1] = make_int4((int)o4, (int)o5, (int)o6, (int)o7);
        }
    } else {
        // ---- fp32 -> fp16 convert branch ----
        const int cb = bid - DQ_BLOCKS;              // 0 .. 4095
        const int base = cb * 1024;                  // float4 units
        #pragma unroll
        for (int j = 0; j < 4; j++) {
            int i = base + j * 256 + tid;
            float4 v = reinterpret_cast<const float4*>(x)[i];
            __half2 a = __floats2half2_rn(v.x, v.y);
            __half2 b = __floats2half2_rn(v.z, v.w);
            uint2 st = make_uint2(*reinterpret_cast<uint32_t*>(&a),
                                  *reinterpret_cast<uint32_t*>(&b));
            reinterpret_cast<uint2*>(g_Xh)[i] = st;
        }
    }
}

// ---------------------------------------------------------------------------
// GEMM: out[m][n] = sum_k Xh[m][k]*Wh[n][k]
//   FROZEN R13 mainloop + config (best: 665us, tensor=69.5%): persistent
//   296 CTAs, CTA 128x128x32, 4 warps (64x64 warp tile), 2 CTAs/SM, NSTG=4,
//   RSTR=40 pad (conflict-free ldmatrix), N-fast tile raster.
//   R17 single change: the NEXT tile's 3-stage pipeline prologue is issued
//   BEFORE the current tile's epilogue, so the fill latency hides under the
//   epilogue's register->gmem stores (disjoint resources; smem stages are
//   fully consumed at mainloop exit, made globally visible by one sync).
// ---------------------------------------------------------------------------
#define BM 128
#define BN 128
#define BK 32
#define NSTG 4
#define RSTR 40                         // halves per padded row
#define A_ELE (BM * RSTR)               // 5120 halves
#define B_ELE (BN * RSTR)               // 5120 halves
#define STG_ELE (A_ELE + B_ELE)         // 10240 halves (20 KB)
#define SMEM_BYTES (NSTG * STG_ELE * 2) // 81920 B per CTA (x2 = 160 KB/SM)
#define NK (INF / BK)                   // 256 k-iters
#define NTILE_N (OUTF / BN)             // 64
#define NTILES  (NTILE_N * (SEQ / BM))  // 1024
#define GRID_CTAS 296                   // 2 CTAs/SM x 148 SMs

__global__ void __launch_bounds__(128, 2) gemm_kernel(float* __restrict__ out) {
    extern __shared__ __half sm[];
    const uint32_t sbase = smem_u32(sm);
    const int tid = threadIdx.x;
    const int wid = tid >> 5, lane = tid & 31;
    const int wm = (wid & 1) * 64;       // warp tile M offset in CTA
    const int wn = (wid >> 1) * 64;      // warp tile N offset in CTA

    // ldmatrix per-lane row/col-chunk mapping (matches m16n8k16 frag layouts)
    const int a_row = ((lane >> 3) & 1) * 8 + (lane & 7);  // + kc = lane>>4
    const int a_kc  = lane >> 4;
    const int b_row = ((lane >> 4) << 3) + (lane & 7);     // + kc = (lane>>3)&1
    const int b_kc  = (lane >> 3) & 1;

    uint32_t sA[4], sB[4];
    #pragma unroll
    for (int i = 0; i < 4; i++) {
        int idx = tid + i * 128;
        int r = idx >> 2, c = idx & 3;
        sA[i] = (uint32_t)(r * RSTR + c * 8) * 2;
        sB[i] = (uint32_t)(A_ELE + r * RSTR + c * 8) * 2;
    }
    const int er = lane >> 2, ec = (lane & 3) * 2;         // epilogue lane map

    // per-thread gmem row/chunk geometry (tile-independent)
    // slot i: row (tid>>2) + ... recomputed per tile below
    bool primed = false;

    #pragma unroll 1
    for (int t = blockIdx.x; t < NTILES; t += GRID_CTAS) {
        const int n0 = (t % NTILE_N) * BN;   // N fast
        const int m0 = (t / NTILE_N) * BM;

        const __half* gA[4]; const __half* gB[4];
        #pragma unroll
        for (int i = 0; i < 4; i++) {
            int idx = tid + i * 128;
            int r = idx >> 2, c = idx & 3;
            gA[i] = g_Xh + (size_t)(m0 + r) * INF + c * 8;
            gB[i] = g_Wh + (size_t)(n0 + r) * INF + c * 8;
        }

        float acc[4][8][4];
        #pragma unroll
        for (int mi = 0; mi < 4; mi++)
            #pragma unroll
            for (int nj = 0; nj < 8; nj++)
                acc[mi][nj][0] = acc[mi][nj][1] = acc[mi][nj][2] = acc[mi][nj][3] = 0.f;

        auto issue = [&](int kt, int s) {
            const uint32_t so = sbase + (uint32_t)(s * STG_ELE) * 2;
            const int ko = kt * BK;
            #pragma unroll
            for (int i = 0; i < 4; i++) {
                cp16(so + sA[i], gA[i] + ko);
                cp16(so + sB[i], gB[i] + ko);
            }
        };

        if (!primed) {      // first tile only; later tiles pre-issued below
            #pragma unroll
            for (int s = 0; s < NSTG - 1; s++) { issue(s, s); cp_commit(); }
        }
        primed = true;

        #pragma unroll 1
        for (int kt = 0; kt < NK; kt++) {
            cp_wait<NSTG - 2>();
            __syncthreads();

            const uint32_t sa = sbase + (uint32_t)((kt % NSTG) * STG_ELE) * 2;
            const uint32_t sb = sa + (uint32_t)A_ELE * 2;

            #pragma unroll
            for (int ks = 0; ks < 2; ks++) {
                uint32_t a[4][4], b[4][4];
                #pragma unroll
                for (int mi = 0; mi < 4; mi++) {
                    uint32_t ad = sa + (uint32_t)((wm + mi * 16 + a_row) * RSTR
                                                  + ks * 16 + a_kc * 8) * 2;
                    LDSM4(a[mi], ad);
                }
                #pragma unroll
                for (int p = 0; p < 4; p++) {
                    uint32_t bd = sb + (uint32_t)((wn + p * 16 + b_row) * RSTR
                                                  + ks * 16 + b_kc * 8) * 2;
                    LDSM4(b[p], bd);
                }
                #pragma unroll
                for (int mi = 0; mi < 4; mi++)
                    #pragma unroll
                    for (int nj = 0; nj < 8; nj++)
                        MMA16816(acc[mi][nj], a[mi],
                                 b[nj >> 1][(nj & 1) * 2], b[nj >> 1][(nj & 1) * 2 + 1]);
            }

            const int nk = kt + NSTG - 1;
            if (nk < NK) issue(nk, nk % NSTG);
            cp_commit();
        }

        // ---- pre-issue NEXT tile's prologue: fill hides under epilogue ----
        const int t2 = t + GRID_CTAS;
        if (t2 < NTILES) {
            cp_wait<0>();          // drain empty trailing groups
            __syncthreads();       // all warps done reading final stages
            const int nn0 = (t2 % NTILE_N) * BN;
            const int mm0 = (t2 / NTILE_N) * BM;
            #pragma unroll
            for (int s = 0; s < NSTG - 1; s++) {
                const uint32_t so = sbase + (uint32_t)(s * STG_ELE) * 2;
                const int ko = s * BK;
                #pragma unroll
                for (int i = 0; i < 4; i++) {
                    int idx = tid + i * 128;
                    int r = idx >> 2, c = idx & 3;
                    cp16(so + sA[i],
                         g_Xh + (size_t)(mm0 + r) * INF + c * 8 + ko);
                    cp16(so + sB[i],
                         g_Wh + (size_t)(nn0 + r) * INF + c * 8 + ko);
                }
                cp_commit();
            }
        }

        // Epilogue: c0,c1 -> (row lane/4, col (lane%4)*2); c2,c3 -> row+8
        #pragma unroll
        for (int mi = 0; mi < 4; mi++) {
            #pragma unroll
            for (int nj = 0; nj < 8; nj++) {
                float* p = out + (size_t)(m0 + wm + mi * 16 + er) * OUTF
                               + (n0 + wn + nj * 8 + ec);
                *reinterpret_cast<float2*>(p) =
                    make_float2(acc[mi][nj][0], acc[mi][nj][1]);
                *reinterpret_cast<float2*>(p + 8 * OUTF) =
                    make_float2(acc[mi][nj][2], acc[mi][nj][3]);
            }
        }
    }
}

// ---------------------------------------------------------------------------
extern "C" void kernel_launch(void* const* d_in, const int* in_sizes, int n_in,
                              void* d_out, int out_size) {
    const float* x   = (const float*)d_in[0];   // (1, 2048, 8192) fp32
    const int*   qw  = (const int*)  d_in[1];   // (8192, 2048)    int32
    const float* lut = (const float*)d_in[2];   // (8192, 16)      fp32
    float* out = (float*)d_out;                 // (1, 2048, 8192) fp32

    cudaFuncSetAttribute(gemm_kernel,
                         cudaFuncAttributeMaxDynamicSharedMemorySize, SMEM_BYTES);

    prep_kernel<<<PREP_GRID, 256>>>(x, qw, lut);
    gemm_kernel<<<GRID_CTAS, 128, SMEM_BYTES>>>(out);
}